// round 2
// baseline (speedup 1.0000x reference)
#include <cuda_runtime.h>
#include <math.h>

#define NN 100000
#define EE 1600000
#define HH 128
#define GG 1000
#define CC 10

// ---------------- scratch (allocation-free: __device__ globals) ----------------
__device__ __align__(16) float g_h[NN * HH];     // h = X @ W
__device__ __align__(16) float g_acc[NN * HH];   // aggregation accumulator
__device__ __align__(16) float g_x[NN * HH];     // layer activations
__device__ __align__(16) float g_dinv[NN];       // deg then 1/sqrt(deg)
__device__ __align__(16) unsigned g_pool[GG * HH];

// ---------------- degree / norm ----------------
__global__ void deg_init() {
    int i = blockIdx.x * blockDim.x + threadIdx.x;
    if (i < NN) g_dinv[i] = 1.0f;  // self-loop contributes 1
}
__global__ void deg_count(const int* __restrict__ ei) {
    int e = blockIdx.x * blockDim.x + threadIdx.x;
    if (e < EE) atomicAdd(&g_dinv[ei[EE + e]], 1.0f);
}
__global__ void deg_finish() {
    int i = blockIdx.x * blockDim.x + threadIdx.x;
    if (i < NN) g_dinv[i] = rsqrtf(g_dinv[i]);
}

// ---------------- GEMM: [nrows,128] @ [128,128] -> g_h ----------------
// Block: 256 threads, tile 64 rows x 128 cols. W fully staged in smem (64KB),
// A tile 64x128 (32KB). Thread micro-tile: 8 rows x 4 cols.
__global__ void gemm128(const float* __restrict__ X, const float* __restrict__ W,
                        int use_internal_x) {
    extern __shared__ float sm[];
    float* Ws = sm;              // 128*128
    float* As = sm + 128 * 128;  // 64*128
    const float* Xp = use_internal_x ? g_x : X;

    int tid = threadIdx.x;
    const float4* W4 = (const float4*)W;
    float4* Ws4 = (float4*)Ws;
#pragma unroll 4
    for (int i = tid; i < 128 * 32; i += 256) Ws4[i] = W4[i];

    int row0 = blockIdx.x * 64;
    const float4* X4 = (const float4*)Xp;
    float4* As4 = (float4*)As;
#pragma unroll 4
    for (int i = tid; i < 64 * 32; i += 256) {
        int r = i >> 5, c = i & 31;
        int gr = row0 + r;
        As4[i] = (gr < NN) ? X4[gr * 32 + c] : make_float4(0.f, 0.f, 0.f, 0.f);
    }
    __syncthreads();

    int cbase = (tid & 31) * 4;  // cols cbase..cbase+3
    int rbase = (tid >> 5) * 8;  // rows rbase..rbase+7 (warp-uniform -> LDS broadcast)

    float acc[8][4];
#pragma unroll
    for (int i = 0; i < 8; i++)
#pragma unroll
        for (int j = 0; j < 4; j++) acc[i][j] = 0.f;

#pragma unroll 4
    for (int k0 = 0; k0 < 128; k0 += 4) {
        float4 b0 = *(const float4*)&Ws[(k0 + 0) * 128 + cbase];
        float4 b1 = *(const float4*)&Ws[(k0 + 1) * 128 + cbase];
        float4 b2 = *(const float4*)&Ws[(k0 + 2) * 128 + cbase];
        float4 b3 = *(const float4*)&Ws[(k0 + 3) * 128 + cbase];
#pragma unroll
        for (int i = 0; i < 8; i++) {
            float4 a = *(const float4*)&As[(rbase + i) * 128 + k0];
            acc[i][0] += a.x * b0.x + a.y * b1.x + a.z * b2.x + a.w * b3.x;
            acc[i][1] += a.x * b0.y + a.y * b1.y + a.z * b2.y + a.w * b3.y;
            acc[i][2] += a.x * b0.z + a.y * b1.z + a.z * b2.z + a.w * b3.z;
            acc[i][3] += a.x * b0.w + a.y * b1.w + a.z * b2.w + a.w * b3.w;
        }
    }

#pragma unroll
    for (int i = 0; i < 8; i++) {
        int gr = row0 + rbase + i;
        if (gr < NN)
            *(float4*)&g_h[gr * 128 + cbase] =
                make_float4(acc[i][0], acc[i][1], acc[i][2], acc[i][3]);
    }
}

// ---------------- self-loop init: acc = dinv^2 * h ----------------
__global__ void selfloop_init() {
    int j = blockIdx.x * blockDim.x + threadIdx.x;  // over NN*32 float4s
    if (j < NN * 32) {
        int node = j >> 5;
        float s = g_dinv[node];
        float s2 = s * s;
        float4 h = ((const float4*)g_h)[j];
        ((float4*)g_acc)[j] = make_float4(h.x * s2, h.y * s2, h.z * s2, h.w * s2);
    }
}

// ---------------- edge scatter: acc[dst] += dinv[src]*dinv[dst]*h[src] ----------------
// One warp per edge; lane = one float4 of the 128-wide feature row.
__global__ void edge_scatter(const int* __restrict__ ei) {
    int warp = (blockIdx.x * blockDim.x + threadIdx.x) >> 5;
    int lane = threadIdx.x & 31;
    if (warp >= EE) return;
    int s = ei[warp];
    int d = ei[EE + warp];
    float nrm = g_dinv[s] * g_dinv[d];
    float4 h = ((const float4*)g_h)[s * 32 + lane];
    float4 v = make_float4(h.x * nrm, h.y * nrm, h.z * nrm, h.w * nrm);
    float* p = &g_acc[d * 128 + lane * 4];
    asm volatile("red.global.add.v4.f32 [%0], {%1,%2,%3,%4};" ::"l"(p), "f"(v.x),
                 "f"(v.y), "f"(v.z), "f"(v.w)
                 : "memory");
}

// ---------------- bias + ELU -> g_x ----------------
__global__ void bias_elu(const float* __restrict__ b) {
    int j = blockIdx.x * blockDim.x + threadIdx.x;  // NN*32 float4s
    if (j < NN * 32) {
        int f4 = (j & 31) * 4;
        float4 a = ((const float4*)g_acc)[j];
        float4 bb = *(const float4*)&b[f4];
        float vx = a.x + bb.x, vy = a.y + bb.y, vz = a.z + bb.z, vw = a.w + bb.w;
        vx = vx > 0.f ? vx : expm1f(vx);
        vy = vy > 0.f ? vy : expm1f(vy);
        vz = vz > 0.f ? vz : expm1f(vz);
        vw = vw > 0.f ? vw : expm1f(vw);
        ((float4*)g_x)[j] = make_float4(vx, vy, vz, vw);
    }
}

// ---------------- segment max pool (monotonic uint encoding) ----------------
__device__ __forceinline__ unsigned enc_f(float x) {
    unsigned u = __float_as_uint(x);
    return (u & 0x80000000u) ? ~u : (u | 0x80000000u);
}
__device__ __forceinline__ float dec_f(unsigned e) {
    return (e & 0x80000000u) ? __uint_as_float(e ^ 0x80000000u)
                             : __uint_as_float(~e);
}

__global__ void pool_init() {
    int j = blockIdx.x * blockDim.x + threadIdx.x;
    if (j < GG * HH) g_pool[j] = 0x007FFFFFu;  // enc(-inf)
}
__global__ void pool_max(const int* __restrict__ batch) {
    int j = blockIdx.x * blockDim.x + threadIdx.x;  // NN*32 float4s
    if (j < NN * 32) {
        int node = j >> 5;
        int g = batch[node];
        float4 v = ((const float4*)g_x)[j];
        unsigned* p = &g_pool[g * 128 + (j & 31) * 4];
        atomicMax(&p[0], enc_f(v.x));
        atomicMax(&p[1], enc_f(v.y));
        atomicMax(&p[2], enc_f(v.z));
        atomicMax(&p[3], enc_f(v.w));
    }
}

// ---------------- head: logits = pooled @ Wl + bl, softmax ----------------
__global__ void head(const float* __restrict__ Wl, const float* __restrict__ bl,
                     float* __restrict__ out) {
    int warp = (blockIdx.x * blockDim.x + threadIdx.x) >> 5;
    int lane = threadIdx.x & 31;
    if (warp >= GG) return;
    float part[CC];
#pragma unroll
    for (int c = 0; c < CC; c++) part[c] = 0.f;
    for (int f = lane; f < HH; f += 32) {
        float p = dec_f(g_pool[warp * HH + f]);
        if (p < -3.0e38f) p = 0.0f;  // empty-segment guard (-inf)
#pragma unroll
        for (int c = 0; c < CC; c++) part[c] += p * Wl[f * CC + c];
    }
#pragma unroll
    for (int c = 0; c < CC; c++)
        for (int off = 16; off; off >>= 1)
            part[c] += __shfl_xor_sync(0xffffffffu, part[c], off);
    if (lane == 0) {
        float lg[CC];
        float m = -3.4e38f;
#pragma unroll
        for (int c = 0; c < CC; c++) {
            lg[c] = part[c] + bl[c];
            m = fmaxf(m, lg[c]);
        }
        float sum = 0.f;
#pragma unroll
        for (int c = 0; c < CC; c++) {
            lg[c] = expf(lg[c] - m);
            sum += lg[c];
        }
        float inv = 1.0f / sum;
#pragma unroll
        for (int c = 0; c < CC; c++) out[warp * CC + c] = lg[c] * inv;
    }
}

// ---------------- launcher ----------------
extern "C" void kernel_launch(void* const* d_in, const int* in_sizes, int n_in,
                              void* d_out, int out_size) {
    const float* x = (const float*)d_in[0];
    const int* ei = (const int*)d_in[1];      // edge_index [2,E] int32
    const int* batch = (const int*)d_in[2];   // [N] int32
    const float* W0 = (const float*)d_in[3];
    const float* b0 = (const float*)d_in[4];
    const float* W1 = (const float*)d_in[5];
    const float* b1 = (const float*)d_in[6];
    const float* W2 = (const float*)d_in[7];
    const float* b2 = (const float*)d_in[8];
    const float* Wl = (const float*)d_in[9];
    const float* bl = (const float*)d_in[10];
    float* out = (float*)d_out;

    const int T = 256;
    const int gemm_smem = (128 * 128 + 64 * 128) * sizeof(float);  // 96KB
    cudaFuncSetAttribute(gemm128, cudaFuncAttributeMaxDynamicSharedMemorySize,
                         gemm_smem);

    // degrees / norms
    deg_init<<<(NN + T - 1) / T, T>>>();
    deg_count<<<(EE + T - 1) / T, T>>>(ei);
    deg_finish<<<(NN + T - 1) / T, T>>>();

    const int gemm_blocks = (NN + 63) / 64;
    const int elem_blocks = (NN * 32 + T - 1) / T;   // float4 elementwise over N*H
    const int edge_blocks = (EE * 32 + T - 1) / T;   // warp per edge

    const float* Ws[3] = {W0, W1, W2};
    const float* bs[3] = {b0, b1, b2};
    for (int l = 0; l < 3; l++) {
        gemm128<<<gemm_blocks, T, gemm_smem>>>(l == 0 ? x : nullptr, Ws[l],
                                               l == 0 ? 0 : 1);
        selfloop_init<<<elem_blocks, T>>>();
        edge_scatter<<<edge_blocks, T>>>(ei);
        bias_elu<<<elem_blocks, T>>>(bs[l]);
    }

    pool_init<<<(GG * HH + T - 1) / T, T>>>();
    pool_max<<<elem_blocks, T>>>(batch);
    head<<<(GG + 7) / 8, T>>>(Wl, bl, out);
}

// round 3
// speedup vs baseline: 1.7086x; 1.7086x over previous
#include <cuda_runtime.h>
#include <math.h>

#define NN 100000
#define EE 1600000
#define HH 128
#define GG 1000
#define CC 10
#define NB_SCAN ((NN + 255) / 256)   // 391

// ---------------- scratch (allocation-free: __device__ globals) ----------------
__device__ __align__(16) float g_h[NN * HH];     // h = X @ W
__device__ __align__(16) float g_x[NN * HH];     // layer activations
__device__ __align__(16) float g_dinv[NN];       // 1/sqrt(deg)
__device__ __align__(16) int g_cnt[NN];          // edge-only in-degree
__device__ __align__(16) int g_rowptr[NN];       // CSR row start (exclusive scan)
__device__ __align__(16) int g_fill[NN];         // fill cursors
__device__ __align__(16) int g_bsum[NB_SCAN];    // scan block sums
__device__ __align__(16) int g_boff[NB_SCAN];    // scan block offsets
__device__ __align__(16) int g_col[EE];          // CSR src indices
__device__ __align__(16) float g_wgt[EE];        // dinv[src] per edge
__device__ __align__(16) unsigned g_pool[GG * HH];

// ---------------- degree ----------------
__global__ void deg_init() {
    int i = blockIdx.x * blockDim.x + threadIdx.x;
    if (i < NN) g_cnt[i] = 0;
}
__global__ void deg_count(const int* __restrict__ ei) {
    int e = blockIdx.x * blockDim.x + threadIdx.x;
    if (e < EE) atomicAdd(&g_cnt[ei[EE + e]], 1);
}
__global__ void deg_finish() {
    int i = blockIdx.x * blockDim.x + threadIdx.x;
    if (i < NN) g_dinv[i] = rsqrtf(1.0f + (float)g_cnt[i]);  // +1 self-loop
}

// ---------------- exclusive scan of g_cnt -> g_rowptr (3 kernels) ----------------
__global__ void scan1() {
    __shared__ int s[256];
    int tid = threadIdx.x;
    int i = blockIdx.x * 256 + tid;
    int v = (i < NN) ? g_cnt[i] : 0;
    s[tid] = v;
    __syncthreads();
#pragma unroll
    for (int off = 1; off < 256; off <<= 1) {
        int t = (tid >= off) ? s[tid - off] : 0;
        __syncthreads();
        s[tid] += t;
        __syncthreads();
    }
    if (i < NN) g_rowptr[i] = s[tid] - v;  // exclusive within block
    if (tid == 255) g_bsum[blockIdx.x] = s[255];
}
__global__ void scan2() {
    __shared__ int s[512];
    int tid = threadIdx.x;
    int v = (tid < NB_SCAN) ? g_bsum[tid] : 0;
    s[tid] = v;
    __syncthreads();
#pragma unroll
    for (int off = 1; off < 512; off <<= 1) {
        int t = (tid >= off) ? s[tid - off] : 0;
        __syncthreads();
        s[tid] += t;
        __syncthreads();
    }
    if (tid < NB_SCAN) g_boff[tid] = s[tid] - v;
}
__global__ void scan3() {
    int i = blockIdx.x * blockDim.x + threadIdx.x;
    if (i < NN) {
        g_rowptr[i] += g_boff[i >> 8];
        g_fill[i] = 0;
    }
}

// ---------------- CSR fill (order within a row is nondeterministic but sums
// are validated with tolerance) ----------------
__global__ void csr_fill(const int* __restrict__ ei) {
    int e = blockIdx.x * blockDim.x + threadIdx.x;
    if (e < EE) {
        int s = ei[e];
        int d = ei[EE + e];
        int pos = g_rowptr[d] + atomicAdd(&g_fill[d], 1);
        g_col[pos] = s;
        g_wgt[pos] = g_dinv[s];
    }
}

// ---------------- GEMM: [NN,128] @ [128,128] -> g_h ----------------
__global__ void gemm128(const float* __restrict__ X, const float* __restrict__ W,
                        int use_internal_x) {
    extern __shared__ float sm[];
    float* Ws = sm;              // 128*128
    float* As = sm + 128 * 128;  // 64*128
    const float* Xp = use_internal_x ? g_x : X;

    int tid = threadIdx.x;
    const float4* W4 = (const float4*)W;
    float4* Ws4 = (float4*)Ws;
#pragma unroll 4
    for (int i = tid; i < 128 * 32; i += 256) Ws4[i] = W4[i];

    int row0 = blockIdx.x * 64;
    const float4* X4 = (const float4*)Xp;
    float4* As4 = (float4*)As;
#pragma unroll 4
    for (int i = tid; i < 64 * 32; i += 256) {
        int r = i >> 5, c = i & 31;
        int gr = row0 + r;
        As4[i] = (gr < NN) ? X4[gr * 32 + c] : make_float4(0.f, 0.f, 0.f, 0.f);
    }
    __syncthreads();

    int cbase = (tid & 31) * 4;
    int rbase = (tid >> 5) * 8;

    float acc[8][4];
#pragma unroll
    for (int i = 0; i < 8; i++)
#pragma unroll
        for (int j = 0; j < 4; j++) acc[i][j] = 0.f;

#pragma unroll 4
    for (int k0 = 0; k0 < 128; k0 += 4) {
        float4 b0 = *(const float4*)&Ws[(k0 + 0) * 128 + cbase];
        float4 b1 = *(const float4*)&Ws[(k0 + 1) * 128 + cbase];
        float4 b2 = *(const float4*)&Ws[(k0 + 2) * 128 + cbase];
        float4 b3 = *(const float4*)&Ws[(k0 + 3) * 128 + cbase];
#pragma unroll
        for (int i = 0; i < 8; i++) {
            float4 a = *(const float4*)&As[(rbase + i) * 128 + k0];
            acc[i][0] += a.x * b0.x + a.y * b1.x + a.z * b2.x + a.w * b3.x;
            acc[i][1] += a.x * b0.y + a.y * b1.y + a.z * b2.y + a.w * b3.y;
            acc[i][2] += a.x * b0.z + a.y * b1.z + a.z * b2.z + a.w * b3.z;
            acc[i][3] += a.x * b0.w + a.y * b1.w + a.z * b2.w + a.w * b3.w;
        }
    }

#pragma unroll
    for (int i = 0; i < 8; i++) {
        int gr = row0 + rbase + i;
        if (gr < NN)
            *(float4*)&g_h[gr * 128 + cbase] =
                make_float4(acc[i][0], acc[i][1], acc[i][2], acc[i][3]);
    }
}

// ---------------- pool encode helpers ----------------
__device__ __forceinline__ unsigned enc_f(float x) {
    unsigned u = __float_as_uint(x);
    return (u & 0x80000000u) ? ~u : (u | 0x80000000u);
}
__device__ __forceinline__ float dec_f(unsigned e) {
    return (e & 0x80000000u) ? __uint_as_float(e ^ 0x80000000u)
                             : __uint_as_float(~e);
}

// ---------------- fused gather: per-node aggregate + self-loop + bias + ELU ----
// one warp per dst node; lane owns one float4 (4 features) of the 128-wide row
__global__ void gather_fused(const float* __restrict__ bias,
                             const int* __restrict__ batch, int do_pool) {
    int warp = (blockIdx.x * blockDim.x + threadIdx.x) >> 5;
    int lane = threadIdx.x & 31;
    if (warp >= NN) return;
    int d = warp;
    int beg = g_rowptr[d];
    int end = beg + g_cnt[d];
    const float4* h4 = (const float4*)g_h;

    float4 acc = make_float4(0.f, 0.f, 0.f, 0.f);
    for (int base = beg; base < end; base += 32) {
        int n = min(32, end - base);
        int c = 0;
        float w = 0.f;
        if (lane < n) {
            c = g_col[base + lane];
            w = g_wgt[base + lane];
        }
#pragma unroll 4
        for (int j = 0; j < n; j++) {
            int s = __shfl_sync(0xffffffffu, c, j);
            float ww = __shfl_sync(0xffffffffu, w, j);
            float4 hv = h4[s * 32 + lane];
            acc.x += ww * hv.x;
            acc.y += ww * hv.y;
            acc.z += ww * hv.z;
            acc.w += ww * hv.w;
        }
    }
    float dd = g_dinv[d];
    float4 hs = h4[d * 32 + lane];
    float4 bb = *(const float4*)&bias[lane * 4];
    float vx = dd * (acc.x + dd * hs.x) + bb.x;
    float vy = dd * (acc.y + dd * hs.y) + bb.y;
    float vz = dd * (acc.z + dd * hs.z) + bb.z;
    float vw = dd * (acc.w + dd * hs.w) + bb.w;
    vx = vx > 0.f ? vx : expm1f(vx);
    vy = vy > 0.f ? vy : expm1f(vy);
    vz = vz > 0.f ? vz : expm1f(vz);
    vw = vw > 0.f ? vw : expm1f(vw);
    ((float4*)g_x)[d * 32 + lane] = make_float4(vx, vy, vz, vw);

    if (do_pool) {
        int g = batch[d];
        unsigned* p = &g_pool[g * 128 + lane * 4];
        atomicMax(&p[0], enc_f(vx));
        atomicMax(&p[1], enc_f(vy));
        atomicMax(&p[2], enc_f(vz));
        atomicMax(&p[3], enc_f(vw));
    }
}

__global__ void pool_init() {
    int j = blockIdx.x * blockDim.x + threadIdx.x;
    if (j < GG * HH) g_pool[j] = 0x007FFFFFu;  // enc(-inf)
}

// ---------------- head ----------------
__global__ void head(const float* __restrict__ Wl, const float* __restrict__ bl,
                     float* __restrict__ out) {
    int warp = (blockIdx.x * blockDim.x + threadIdx.x) >> 5;
    int lane = threadIdx.x & 31;
    if (warp >= GG) return;
    float part[CC];
#pragma unroll
    for (int c = 0; c < CC; c++) part[c] = 0.f;
    for (int f = lane; f < HH; f += 32) {
        float p = dec_f(g_pool[warp * HH + f]);
        if (p < -3.0e38f) p = 0.0f;  // empty-segment guard
#pragma unroll
        for (int c = 0; c < CC; c++) part[c] += p * Wl[f * CC + c];
    }
#pragma unroll
    for (int c = 0; c < CC; c++)
        for (int off = 16; off; off >>= 1)
            part[c] += __shfl_xor_sync(0xffffffffu, part[c], off);
    if (lane == 0) {
        float lg[CC];
        float m = -3.4e38f;
#pragma unroll
        for (int c = 0; c < CC; c++) {
            lg[c] = part[c] + bl[c];
            m = fmaxf(m, lg[c]);
        }
        float sum = 0.f;
#pragma unroll
        for (int c = 0; c < CC; c++) {
            lg[c] = expf(lg[c] - m);
            sum += lg[c];
        }
        float inv = 1.0f / sum;
#pragma unroll
        for (int c = 0; c < CC; c++) out[warp * CC + c] = lg[c] * inv;
    }
}

// ---------------- launcher ----------------
extern "C" void kernel_launch(void* const* d_in, const int* in_sizes, int n_in,
                              void* d_out, int out_size) {
    const float* x = (const float*)d_in[0];
    const int* ei = (const int*)d_in[1];
    const int* batch = (const int*)d_in[2];
    const float* W0 = (const float*)d_in[3];
    const float* b0 = (const float*)d_in[4];
    const float* W1 = (const float*)d_in[5];
    const float* b1 = (const float*)d_in[6];
    const float* W2 = (const float*)d_in[7];
    const float* b2 = (const float*)d_in[8];
    const float* Wl = (const float*)d_in[9];
    const float* bl = (const float*)d_in[10];
    float* out = (float*)d_out;

    const int T = 256;
    const int gemm_smem = (128 * 128 + 64 * 128) * sizeof(float);
    cudaFuncSetAttribute(gemm128, cudaFuncAttributeMaxDynamicSharedMemorySize,
                         gemm_smem);

    // degrees + CSR build
    deg_init<<<(NN + T - 1) / T, T>>>();
    deg_count<<<(EE + T - 1) / T, T>>>(ei);
    deg_finish<<<(NN + T - 1) / T, T>>>();
    scan1<<<NB_SCAN, 256>>>();
    scan2<<<1, 512>>>();
    scan3<<<(NN + T - 1) / T, T>>>();
    csr_fill<<<(EE + T - 1) / T, T>>>(ei);
    pool_init<<<(GG * HH + T - 1) / T, T>>>();

    const int gemm_blocks = (NN + 63) / 64;
    const int gather_blocks = (NN * 32 + T - 1) / T;

    const float* Ws[3] = {W0, W1, W2};
    const float* bs[3] = {b0, b1, b2};
    for (int l = 0; l < 3; l++) {
        gemm128<<<gemm_blocks, T, gemm_smem>>>(l == 0 ? x : nullptr, Ws[l],
                                               l == 0 ? 0 : 1);
        gather_fused<<<gather_blocks, T>>>(bs[l], batch, l == 2 ? 1 : 0);
    }

    head<<<(GG + 7) / 8, T>>>(Wl, bl, out);
}

// round 4
// speedup vs baseline: 1.9373x; 1.1338x over previous
#include <cuda_runtime.h>
#include <cuda_bf16.h>
#include <math.h>

#define NN 100000
#define NPAD 100096            // 782 * 128
#define EE 1600000
#define HH 128
#define GG 1000
#define CC 10
#define NB_SCAN ((NN + 255) / 256)   // 391
#define KSTR 136               // smem W row stride in bf16 (272B, 16B-aligned)

// ---------------- scratch ----------------
__device__ __align__(16) float g_h[NN * HH];                 // GEMM output (fp32)
__device__ __align__(16) __nv_bfloat16 g_ahi[NPAD * HH];     // activation hi
__device__ __align__(16) __nv_bfloat16 g_alo[NPAD * HH];     // activation lo
__device__ __align__(16) float g_dinv[NN];
__device__ __align__(16) int g_cnt[NN];
__device__ __align__(16) int g_rowptr[NN];
__device__ __align__(16) int g_fill[NN];
__device__ __align__(16) int g_bsum[NB_SCAN];
__device__ __align__(16) int g_boff[NB_SCAN];
__device__ __align__(16) int g_col[EE];
__device__ __align__(16) float g_wgt[EE];
__device__ __align__(16) unsigned g_pool[GG * HH];

// ---------------- degree ----------------
__global__ void deg_init() {
    int i = blockIdx.x * blockDim.x + threadIdx.x;
    if (i < NN) g_cnt[i] = 0;
}
__global__ void deg_count(const int* __restrict__ ei) {
    int e = blockIdx.x * blockDim.x + threadIdx.x;
    if (e < EE) atomicAdd(&g_cnt[ei[EE + e]], 1);
}
__global__ void deg_finish() {
    int i = blockIdx.x * blockDim.x + threadIdx.x;
    if (i < NN) g_dinv[i] = rsqrtf(1.0f + (float)g_cnt[i]);
}

// ---------------- exclusive scan ----------------
__global__ void scan1() {
    __shared__ int s[256];
    int tid = threadIdx.x;
    int i = blockIdx.x * 256 + tid;
    int v = (i < NN) ? g_cnt[i] : 0;
    s[tid] = v;
    __syncthreads();
#pragma unroll
    for (int off = 1; off < 256; off <<= 1) {
        int t = (tid >= off) ? s[tid - off] : 0;
        __syncthreads();
        s[tid] += t;
        __syncthreads();
    }
    if (i < NN) g_rowptr[i] = s[tid] - v;
    if (tid == 255) g_bsum[blockIdx.x] = s[255];
}
__global__ void scan2() {
    __shared__ int s[512];
    int tid = threadIdx.x;
    int v = (tid < NB_SCAN) ? g_bsum[tid] : 0;
    s[tid] = v;
    __syncthreads();
#pragma unroll
    for (int off = 1; off < 512; off <<= 1) {
        int t = (tid >= off) ? s[tid - off] : 0;
        __syncthreads();
        s[tid] += t;
        __syncthreads();
    }
    if (tid < NB_SCAN) g_boff[tid] = s[tid] - v;
}
__global__ void scan3() {
    int i = blockIdx.x * blockDim.x + threadIdx.x;
    if (i < NN) {
        g_rowptr[i] += g_boff[i >> 8];
        g_fill[i] = 0;
    }
}
__global__ void csr_fill(const int* __restrict__ ei) {
    int e = blockIdx.x * blockDim.x + threadIdx.x;
    if (e < EE) {
        int s = ei[e];
        int d = ei[EE + e];
        int pos = g_rowptr[d] + atomicAdd(&g_fill[d], 1);
        g_col[pos] = s;
        g_wgt[pos] = g_dinv[s];
    }
}

// ---------------- split helpers ----------------
__device__ __forceinline__ void split2(float v, __nv_bfloat16& h, __nv_bfloat16& l) {
    h = __float2bfloat16(v);
    l = __float2bfloat16(v - __bfloat162float(h));
}

__global__ void split_x(const float* __restrict__ X) {
    int i = blockIdx.x * blockDim.x + threadIdx.x;  // over NN*64 float2
    if (i < NN * 64) {
        float2 v = ((const float2*)X)[i];
        __nv_bfloat16 hx, lx, hy, ly;
        split2(v.x, hx, lx);
        split2(v.y, hy, ly);
        ((__nv_bfloat162*)g_ahi)[i] = __nv_bfloat162{hx, hy};
        ((__nv_bfloat162*)g_alo)[i] = __nv_bfloat162{lx, ly};
    }
}
__global__ void pad_zero() {
    int i = blockIdx.x * blockDim.x + threadIdx.x;  // (NPAD-NN)*64 float2
    if (i < (NPAD - NN) * 64) {
        ((__nv_bfloat162*)g_ahi)[NN * 64 + i] = __nv_bfloat162{__nv_bfloat16(0.f), __nv_bfloat16(0.f)};
        ((__nv_bfloat162*)g_alo)[NN * 64 + i] = __nv_bfloat162{__nv_bfloat16(0.f), __nv_bfloat16(0.f)};
    }
}

// ---------------- tensor-core GEMM: [NPAD,128](split bf16) @ [128,128] -> g_h fp32
// block = 256 thr (8 warps), tile 128 rows x 128 cols; warp = 16 rows x 128 cols.
// C = Ahi*Whi + Ahi*Wlo + Alo*Whi  (~fp32 accuracy)
__device__ __forceinline__ void mma_bf16(float c[4], unsigned a0, unsigned a1,
                                         unsigned a2, unsigned a3, unsigned b0,
                                         unsigned b1) {
    asm volatile(
        "mma.sync.aligned.m16n8k16.row.col.f32.bf16.bf16.f32 "
        "{%0,%1,%2,%3}, {%4,%5,%6,%7}, {%8,%9}, {%0,%1,%2,%3};"
        : "+f"(c[0]), "+f"(c[1]), "+f"(c[2]), "+f"(c[3])
        : "r"(a0), "r"(a1), "r"(a2), "r"(a3), "r"(b0), "r"(b1));
}
__device__ __forceinline__ void ldsm4t(unsigned& r0, unsigned& r1, unsigned& r2,
                                       unsigned& r3, unsigned saddr) {
    asm volatile(
        "ldmatrix.sync.aligned.m8n8.x4.trans.shared.b16 {%0,%1,%2,%3}, [%4];"
        : "=r"(r0), "=r"(r1), "=r"(r2), "=r"(r3)
        : "r"(saddr));
}

__global__ __launch_bounds__(256, 2) void gemm_mma(const float* __restrict__ W) {
    extern __shared__ __nv_bfloat16 sw[];
    __nv_bfloat16* Whi = sw;             // [128][KSTR]
    __nv_bfloat16* Wlo = sw + 128 * KSTR;
    int tid = threadIdx.x;

    // stage + split W (row-major [k][n], stride KSTR)
    for (int i = tid; i < 128 * 128; i += 256) {
        int k = i >> 7, n = i & 127;
        __nv_bfloat16 h, l;
        split2(W[i], h, l);
        Whi[k * KSTR + n] = h;
        Wlo[k * KSTR + n] = l;
    }
    __syncthreads();

    unsigned swhi, swlo;
    {
        unsigned base = (unsigned)__cvta_generic_to_shared(sw);
        swhi = base;
        swlo = base + 128 * KSTR * 2;
    }

    int warp = tid >> 5, lane = tid & 31;
    int row0 = blockIdx.x * 128 + warp * 16;
    int g = lane >> 2, t = lane & 3;

    // per-lane ldmatrix address component (within a W array)
    int q = lane >> 3, r = lane & 7;
    int kk_off = (r + ((q & 1) << 3)) * (KSTR * 2);  // k-row byte offset (before +k0)
    int nn_off = ((q >> 1) << 3) * 2;                // n byte offset (before +n0)

    // A word pointers (128 bf16 per row = 64 words)
    const unsigned* pH0 = (const unsigned*)g_ahi + (size_t)(row0 + g) * 64;
    const unsigned* pH1 = pH0 + 8 * 64;
    const unsigned* pL0 = (const unsigned*)g_alo + (size_t)(row0 + g) * 64;
    const unsigned* pL1 = pL0 + 8 * 64;

    float c[16][4];
#pragma unroll
    for (int i = 0; i < 16; i++)
#pragma unroll
        for (int j = 0; j < 4; j++) c[i][j] = 0.f;

    for (int k0 = 0; k0 < 128; k0 += 16) {
        int wi = (k0 >> 1) + t;
        unsigned ah0 = pH0[wi], ah1 = pH1[wi], ah2 = pH0[wi + 4], ah3 = pH1[wi + 4];
        unsigned al0 = pL0[wi], al1 = pL1[wi], al2 = pL0[wi + 4], al3 = pL1[wi + 4];
        unsigned kbase = (unsigned)(k0 * (KSTR * 2)) + kk_off + nn_off;

#pragma unroll
        for (int p = 0; p < 8; p++) {
            unsigned noff = kbase + p * 32;  // n0 = p*16 -> +16*2 bytes
            unsigned bh0, bh1, bh2, bh3, bl0, bl1, bl2, bl3;
            ldsm4t(bh0, bh1, bh2, bh3, swhi + noff);
            ldsm4t(bl0, bl1, bl2, bl3, swlo + noff);
            mma_bf16(c[2 * p],     ah0, ah1, ah2, ah3, bh0, bh1);
            mma_bf16(c[2 * p + 1], ah0, ah1, ah2, ah3, bh2, bh3);
            mma_bf16(c[2 * p],     ah0, ah1, ah2, ah3, bl0, bl1);
            mma_bf16(c[2 * p + 1], ah0, ah1, ah2, ah3, bl2, bl3);
            mma_bf16(c[2 * p],     al0, al1, al2, al3, bh0, bh1);
            mma_bf16(c[2 * p + 1], al0, al1, al2, al3, bh2, bh3);
        }
    }

    // store C (guard rows >= NN)
    int ra = row0 + g, rb = ra + 8;
#pragma unroll
    for (int nt = 0; nt < 16; nt++) {
        int col = nt * 8 + t * 2;
        if (ra < NN) *(float2*)&g_h[(size_t)ra * 128 + col] = make_float2(c[nt][0], c[nt][1]);
        if (rb < NN) *(float2*)&g_h[(size_t)rb * 128 + col] = make_float2(c[nt][2], c[nt][3]);
    }
}

// ---------------- pool encode ----------------
__device__ __forceinline__ unsigned enc_f(float x) {
    unsigned u = __float_as_uint(x);
    return (u & 0x80000000u) ? ~u : (u | 0x80000000u);
}
__device__ __forceinline__ float dec_f(unsigned e) {
    return (e & 0x80000000u) ? __uint_as_float(e ^ 0x80000000u)
                             : __uint_as_float(~e);
}

// ---------------- fused gather ----------------
// one warp per dst node; lane owns one float4 of the 128-wide row.
// writes split bf16 activations (next layer's GEMM input) or pools (last layer)
__global__ void gather_fused(const float* __restrict__ bias,
                             const int* __restrict__ batch, int do_pool) {
    int warp = (blockIdx.x * blockDim.x + threadIdx.x) >> 5;
    int lane = threadIdx.x & 31;
    if (warp >= NN) return;
    int d = warp;
    int beg = g_rowptr[d];
    int end = beg + g_cnt[d];
    const float4* h4 = (const float4*)g_h;

    float4 acc = make_float4(0.f, 0.f, 0.f, 0.f);
    for (int base = beg; base < end; base += 32) {
        int n = min(32, end - base);
        int c = 0;
        float w = 0.f;
        if (lane < n) {
            c = g_col[base + lane];
            w = g_wgt[base + lane];
        }
#pragma unroll 4
        for (int j = 0; j < n; j++) {
            int s = __shfl_sync(0xffffffffu, c, j);
            float ww = __shfl_sync(0xffffffffu, w, j);
            float4 hv = h4[s * 32 + lane];
            acc.x += ww * hv.x;
            acc.y += ww * hv.y;
            acc.z += ww * hv.z;
            acc.w += ww * hv.w;
        }
    }
    float dd = g_dinv[d];
    float4 hs = h4[d * 32 + lane];
    float4 bb = *(const float4*)&bias[lane * 4];
    float vx = dd * (acc.x + dd * hs.x) + bb.x;
    float vy = dd * (acc.y + dd * hs.y) + bb.y;
    float vz = dd * (acc.z + dd * hs.z) + bb.z;
    float vw = dd * (acc.w + dd * hs.w) + bb.w;
    vx = vx > 0.f ? vx : expm1f(vx);
    vy = vy > 0.f ? vy : expm1f(vy);
    vz = vz > 0.f ? vz : expm1f(vz);
    vw = vw > 0.f ? vw : expm1f(vw);

    if (!do_pool) {
        __nv_bfloat16 h0, l0, h1, l1, h2, l2, h3, l3;
        split2(vx, h0, l0);
        split2(vy, h1, l1);
        split2(vz, h2, l2);
        split2(vw, h3, l3);
        __nv_bfloat162* ph = (__nv_bfloat162*)g_ahi + (size_t)d * 64 + lane * 2;
        __nv_bfloat162* pl = (__nv_bfloat162*)g_alo + (size_t)d * 64 + lane * 2;
        ph[0] = __nv_bfloat162{h0, h1};
        ph[1] = __nv_bfloat162{h2, h3};
        pl[0] = __nv_bfloat162{l0, l1};
        pl[1] = __nv_bfloat162{l2, l3};
    } else {
        int g = batch[d];
        unsigned* p = &g_pool[g * 128 + lane * 4];
        atomicMax(&p[0], enc_f(vx));
        atomicMax(&p[1], enc_f(vy));
        atomicMax(&p[2], enc_f(vz));
        atomicMax(&p[3], enc_f(vw));
    }
}

__global__ void pool_init() {
    int j = blockIdx.x * blockDim.x + threadIdx.x;
    if (j < GG * HH) g_pool[j] = 0x007FFFFFu;  // enc(-inf)
}

// ---------------- head ----------------
__global__ void head(const float* __restrict__ Wl, const float* __restrict__ bl,
                     float* __restrict__ out) {
    int warp = (blockIdx.x * blockDim.x + threadIdx.x) >> 5;
    int lane = threadIdx.x & 31;
    if (warp >= GG) return;
    float part[CC];
#pragma unroll
    for (int c = 0; c < CC; c++) part[c] = 0.f;
    for (int f = lane; f < HH; f += 32) {
        float p = dec_f(g_pool[warp * HH + f]);
        if (p < -3.0e38f) p = 0.0f;
#pragma unroll
        for (int c = 0; c < CC; c++) part[c] += p * Wl[f * CC + c];
    }
#pragma unroll
    for (int c = 0; c < CC; c++)
        for (int off = 16; off; off >>= 1)
            part[c] += __shfl_xor_sync(0xffffffffu, part[c], off);
    if (lane == 0) {
        float lg[CC];
        float m = -3.4e38f;
#pragma unroll
        for (int c = 0; c < CC; c++) {
            lg[c] = part[c] + bl[c];
            m = fmaxf(m, lg[c]);
        }
        float sum = 0.f;
#pragma unroll
        for (int c = 0; c < CC; c++) {
            lg[c] = expf(lg[c] - m);
            sum += lg[c];
        }
        float inv = 1.0f / sum;
#pragma unroll
        for (int c = 0; c < CC; c++) out[warp * CC + c] = lg[c] * inv;
    }
}

// ---------------- launcher ----------------
extern "C" void kernel_launch(void* const* d_in, const int* in_sizes, int n_in,
                              void* d_out, int out_size) {
    const float* x = (const float*)d_in[0];
    const int* ei = (const int*)d_in[1];
    const int* batch = (const int*)d_in[2];
    const float* W0 = (const float*)d_in[3];
    const float* b0 = (const float*)d_in[4];
    const float* W1 = (const float*)d_in[5];
    const float* b1 = (const float*)d_in[6];
    const float* W2 = (const float*)d_in[7];
    const float* b2 = (const float*)d_in[8];
    const float* Wl = (const float*)d_in[9];
    const float* bl = (const float*)d_in[10];
    float* out = (float*)d_out;

    const int T = 256;
    const int gemm_smem = 2 * 128 * KSTR * 2;  // 69632 B
    cudaFuncSetAttribute(gemm_mma, cudaFuncAttributeMaxDynamicSharedMemorySize,
                         gemm_smem);

    // degrees + CSR build + init
    deg_init<<<(NN + T - 1) / T, T>>>();
    deg_count<<<(EE + T - 1) / T, T>>>(ei);
    deg_finish<<<(NN + T - 1) / T, T>>>();
    scan1<<<NB_SCAN, 256>>>();
    scan2<<<1, 512>>>();
    scan3<<<(NN + T - 1) / T, T>>>();
    csr_fill<<<(EE + T - 1) / T, T>>>(ei);
    pool_init<<<(GG * HH + T - 1) / T, T>>>();
    split_x<<<(NN * 64 + T - 1) / T, T>>>(x);
    pad_zero<<<((NPAD - NN) * 64 + T - 1) / T, T>>>();

    const int gemm_blocks = NPAD / 128;  // 782
    const int gather_blocks = (NN * 32 + T - 1) / T;

    const float* Ws[3] = {W0, W1, W2};
    const float* bs[3] = {b0, b1, b2};
    for (int l = 0; l < 3; l++) {
        gemm_mma<<<gemm_blocks, T, gemm_smem>>>(Ws[l]);
        gather_fused<<<gather_blocks, T>>>(bs[l], batch, l == 2 ? 1 : 0);
    }

    head<<<(GG + 7) / 8, T>>>(Wl, bl, out);
}